// round 1
// baseline (speedup 1.0000x reference)
#include <cuda_runtime.h>
#include <cstdint>

// Problem constants
#define B_      4
#define N_      4096
#define K_      32
#define H_      128
#define NODES   (B_ * N_)        // 16384
#define EDGES   (NODES * K_)     // 524288
#define LDS_    132              // padded row stride in floats (conflict-free mma frag loads)
#define NTILES  (NODES / 4)      // 4096 tiles of 128 edges (4 nodes)

static const int SMEM_BYTES = 3 * 128 * LDS_ * 4;  // 202752 B: sA + sW1 + sW2

// Scratch (no cudaMalloc allowed)
__device__ float g_P[NODES * H_];     // enc @ W0[:H]
__device__ float g_S[NODES * H_];     // enc @ W0[H:2H] + b0
__device__ float g_msum[NODES * H_];  // sum of valid messages per node
__device__ float g_vcnt[NODES];       // valid edge count per node

// ---------------------------------------------------------------- helpers
__device__ __forceinline__ float to_tf32(float x) {
    uint32_t u;
    asm("cvt.rna.tf32.f32 %0, %1;" : "=r"(u) : "f"(x));
    return __uint_as_float(u);
}
__device__ __forceinline__ float gelu_erf(float x) {
    return 0.5f * x * (1.0f + erff(x * 0.70710678118654752f));
}
__device__ __forceinline__ void mma8(float* c, const uint32_t* a, const uint32_t* b) {
    asm volatile(
        "mma.sync.aligned.m16n8k8.row.col.f32.tf32.tf32.f32 "
        "{%0,%1,%2,%3},{%4,%5,%6,%7},{%8,%9},{%0,%1,%2,%3};\n"
        : "+f"(c[0]), "+f"(c[1]), "+f"(c[2]), "+f"(c[3])
        : "r"(a[0]), "r"(a[1]), "r"(a[2]), "r"(a[3]), "r"(b[0]), "r"(b[1]));
}

// Warp tile: 32 rows (2 m-frags) x 64 cols (8 n-frags), K=128.
// sA: row-major [row*LDS_ + k] (tf32 bits). sW: transposed [n*LDS_ + k] (tf32 bits).
// Both layouts are bank-conflict-free for the m16n8k8 fragment patterns (LDS_%32==4).
__device__ __forceinline__ void warp_gemm(const float* __restrict__ sAv,
                                          const float* __restrict__ sWv,
                                          float acc[2][8][4],
                                          int wm, int wn, int gid, int tig) {
#pragma unroll 4
    for (int k0 = 0; k0 < H_; k0 += 8) {
        uint32_t a[2][4];
#pragma unroll
        for (int i = 0; i < 2; i++) {
            const float* ap = sAv + (wm * 32 + i * 16 + gid) * LDS_ + k0;
            a[i][0] = __float_as_uint(ap[tig]);
            a[i][1] = __float_as_uint(ap[8 * LDS_ + tig]);
            a[i][2] = __float_as_uint(ap[tig + 4]);
            a[i][3] = __float_as_uint(ap[8 * LDS_ + tig + 4]);
        }
#pragma unroll
        for (int j = 0; j < 8; j++) {
            const float* bp = sWv + (wn * 64 + j * 8 + gid) * LDS_ + k0;
            uint32_t b[2] = {__float_as_uint(bp[tig]), __float_as_uint(bp[tig + 4])};
            mma8(acc[0][j], a[0], b);
            mma8(acc[1][j], a[1], b);
        }
    }
}

// ------------------------------------------------- kernel 1: node projections
// P = (atom*mask) @ W0a ; S = (atom*mask) @ W0b + b0.  128 rows per CTA.
__global__ void __launch_bounds__(256, 1)
proj_kernel(const float* __restrict__ atom, const float* __restrict__ mask,
            const float* __restrict__ W0, const float* __restrict__ b0) {
    extern __shared__ float smem[];
    float* sA  = smem;
    float* sWa = smem + 128 * LDS_;
    float* sWb = smem + 2 * 128 * LDS_;
    __shared__ float sB0[128];

    int t = threadIdx.x, lane = t & 31, w = t >> 5;
    int wm = w >> 1, wn = w & 1, gid = lane >> 2, tig = lane & 3;

    if (t < 128) sB0[t] = b0[t];
    for (int i = t; i < 128 * 128; i += 256) {
        int k = i >> 7, n = i & 127;
        sWa[n * LDS_ + k] = to_tf32(W0[i]);                // rows 0..127
        sWb[n * LDS_ + k] = to_tf32(W0[128 * 128 + i]);    // rows 128..255
    }
    {   // load A tile (masked encodings), tf32-rounded
        int r = t >> 1;
        int grow = blockIdx.x * 128 + r;
        float m = mask[grow];
        int c0 = (t & 1) * 64;
        const float4* src = (const float4*)(atom + grow * H_);
#pragma unroll 4
        for (int c = c0; c < c0 + 64; c += 4) {
            float4 a = src[c >> 2];
            float4 o;
            o.x = to_tf32(a.x * m); o.y = to_tf32(a.y * m);
            o.z = to_tf32(a.z * m); o.w = to_tf32(a.w * m);
            *(float4*)(sA + r * LDS_ + c) = o;
        }
    }
    __syncthreads();

    float acc[2][8][4];
#pragma unroll
    for (int i = 0; i < 2; i++)
#pragma unroll
        for (int j = 0; j < 8; j++)
#pragma unroll
            for (int q = 0; q < 4; q++) acc[i][j][q] = 0.f;
    warp_gemm(sA, sWa, acc, wm, wn, gid, tig);
#pragma unroll
    for (int i = 0; i < 2; i++)
#pragma unroll
        for (int j = 0; j < 8; j++) {
            int col = wn * 64 + j * 8 + 2 * tig;
            int r = blockIdx.x * 128 + wm * 32 + i * 16 + gid;
            *(float2*)(g_P + r * H_ + col)       = make_float2(acc[i][j][0], acc[i][j][1]);
            *(float2*)(g_P + (r + 8) * H_ + col) = make_float2(acc[i][j][2], acc[i][j][3]);
        }
#pragma unroll
    for (int i = 0; i < 2; i++)
#pragma unroll
        for (int j = 0; j < 8; j++)
#pragma unroll
            for (int q = 0; q < 4; q++) acc[i][j][q] = 0.f;
    warp_gemm(sA, sWb, acc, wm, wn, gid, tig);
#pragma unroll
    for (int i = 0; i < 2; i++)
#pragma unroll
        for (int j = 0; j < 8; j++) {
            int col = wn * 64 + j * 8 + 2 * tig;
            int r = blockIdx.x * 128 + wm * 32 + i * 16 + gid;
            float be = sB0[col], bo = sB0[col + 1];
            *(float2*)(g_S + r * H_ + col)       = make_float2(acc[i][j][0] + be, acc[i][j][1] + bo);
            *(float2*)(g_S + (r + 8) * H_ + col) = make_float2(acc[i][j][2] + be, acc[i][j][3] + bo);
        }
}

// ------------------------------------------------- kernel 2: fused edge MLP
// Tile = 128 edges = 4 nodes.  h0 = gelu(P[src]+S[self]+d*w0c) -> h1 = gelu(h0@W1+b1)
// -> h2 = gelu(h1@W2+b2) * valid -> per-node column sums into g_msum.
__global__ void __launch_bounds__(256, 1)
edge_kernel(const float* __restrict__ dist, const int* __restrict__ eidx,
            const float* __restrict__ W0, const float* __restrict__ W1,
            const float* __restrict__ b1, const float* __restrict__ W2,
            const float* __restrict__ b2) {
    extern __shared__ float smem[];
    float* sA  = smem;
    float* sW1 = smem + 128 * LDS_;
    float* sW2 = smem + 2 * 128 * LDS_;
    __shared__ int   sSrc[128];
    __shared__ float sValid[128];
    __shared__ float sDist[128];
    __shared__ float sW0c[128];
    __shared__ float sB1[128];
    __shared__ float sB2[128];

    int t = threadIdx.x, lane = t & 31, w = t >> 5;
    int wm = w >> 1, wn = w & 1, gid = lane >> 2, tig = lane & 3;

    if (t < 128) {
        sW0c[t] = W0[256 * 128 + t];
        sB1[t]  = b1[t];
        sB2[t]  = b2[t];
        // per-edge metadata
        int e = t;
        int gnode = blockIdx.x * 4 + (e >> 5);
        int b = gnode >> 12;                 // N_ = 4096
        long long eid = (long long)gnode * K_ + (e & 31);
        int idx = eidx[eid];
        sValid[e] = (idx >= 0) ? 1.0f : 0.0f;
        sSrc[e]   = (b << 12) + (idx >= 0 ? idx : 0);
        sDist[e]  = dist[eid];
    }
    for (int i = t; i < 128 * 128; i += 256) {
        int k = i >> 7, n = i & 127;
        sW1[n * LDS_ + k] = to_tf32(W1[i]);
        sW2[n * LDS_ + k] = to_tf32(W2[i]);
    }
    __syncthreads();

    if (t < 4) {  // valid counts (one node each)
        float c = 0.f;
#pragma unroll
        for (int kk = 0; kk < 32; kk++) c += sValid[t * 32 + kk];
        g_vcnt[blockIdx.x * 4 + t] = c;
    }

    {   // phase A: build h0 tile
        int e = t >> 1;
        int gnode = blockIdx.x * 4 + (e >> 5);
        int src = sSrc[e];
        float d = sDist[e];
        int c0 = (t & 1) * 64;
        const float4* pp = (const float4*)(g_P + src * H_);
        const float4* sp = (const float4*)(g_S + gnode * H_);
#pragma unroll 4
        for (int c = c0; c < c0 + 64; c += 4) {
            float4 p = pp[c >> 2];
            float4 s = sp[c >> 2];
            float4 o;
            o.x = to_tf32(gelu_erf(p.x + s.x + d * sW0c[c]));
            o.y = to_tf32(gelu_erf(p.y + s.y + d * sW0c[c + 1]));
            o.z = to_tf32(gelu_erf(p.z + s.z + d * sW0c[c + 2]));
            o.w = to_tf32(gelu_erf(p.w + s.w + d * sW0c[c + 3]));
            *(float4*)(sA + e * LDS_ + c) = o;
        }
    }
    __syncthreads();

    float acc[2][8][4];
#pragma unroll
    for (int i = 0; i < 2; i++)
#pragma unroll
        for (int j = 0; j < 8; j++)
#pragma unroll
            for (int q = 0; q < 4; q++) acc[i][j][q] = 0.f;
    warp_gemm(sA, sW1, acc, wm, wn, gid, tig);    // layer 2
    __syncthreads();                               // everyone done reading h0
#pragma unroll
    for (int i = 0; i < 2; i++)
#pragma unroll
        for (int j = 0; j < 8; j++) {
            int col = wn * 64 + j * 8 + 2 * tig;
            int r0 = wm * 32 + i * 16 + gid;
            sA[r0 * LDS_ + col]           = to_tf32(gelu_erf(acc[i][j][0] + sB1[col]));
            sA[r0 * LDS_ + col + 1]       = to_tf32(gelu_erf(acc[i][j][1] + sB1[col + 1]));
            sA[(r0 + 8) * LDS_ + col]     = to_tf32(gelu_erf(acc[i][j][2] + sB1[col]));
            sA[(r0 + 8) * LDS_ + col + 1] = to_tf32(gelu_erf(acc[i][j][3] + sB1[col + 1]));
        }
#pragma unroll
    for (int i = 0; i < 2; i++)
#pragma unroll
        for (int j = 0; j < 8; j++)
#pragma unroll
            for (int q = 0; q < 4; q++) acc[i][j][q] = 0.f;
    __syncthreads();
    warp_gemm(sA, sW2, acc, wm, wn, gid, tig);    // layer 3

    // epilogue: gelu + valid mask + sum over the 32 edges of this warp's node
    int gout = blockIdx.x * 4 + wm;
#pragma unroll
    for (int j = 0; j < 8; j++) {
        int col = wn * 64 + j * 8 + 2 * tig;
        float be = sB2[col], bo = sB2[col + 1];
        float se = 0.f, so = 0.f;
#pragma unroll
        for (int i = 0; i < 2; i++) {
            int r0 = wm * 32 + i * 16 + gid;
            float v0 = sValid[r0], v1 = sValid[r0 + 8];
            se += gelu_erf(acc[i][j][0] + be) * v0 + gelu_erf(acc[i][j][2] + be) * v1;
            so += gelu_erf(acc[i][j][1] + bo) * v0 + gelu_erf(acc[i][j][3] + bo) * v1;
        }
        se += __shfl_xor_sync(0xffffffffu, se, 16);
        so += __shfl_xor_sync(0xffffffffu, so, 16);
        se += __shfl_xor_sync(0xffffffffu, se, 8);
        so += __shfl_xor_sync(0xffffffffu, so, 8);
        se += __shfl_xor_sync(0xffffffffu, se, 4);
        so += __shfl_xor_sync(0xffffffffu, so, 4);
        if (gid == 0) *(float2*)(g_msum + gout * H_ + col) = make_float2(se, so);
    }
}

// ------------------------------------------------- kernel 3: update + graph norm
// One block per (batch, feature).  Two passes over N (L2-resident).
__global__ void __launch_bounds__(256)
norm_kernel(const float* __restrict__ atom, const float* __restrict__ mask,
            const float* __restrict__ scale, const float* __restrict__ shift,
            float* __restrict__ out) {
    int bh = blockIdx.x;
    int b = bh >> 7, h = bh & 127;
    int lane = threadIdx.x & 31, wid = threadIdx.x >> 5;

    float s = 0.f, s2 = 0.f, cnt = 0.f;
    for (int n = threadIdx.x; n < N_; n += 256) {
        int g = b * N_ + n;
        float m = mask[g];
        if (m != 0.f) {
            float vc = g_vcnt[g];
            if (vc == 0.f) vc = 1.f;
            float u = (atom[g * H_ + h] + g_msum[g * H_ + h] / vc) * m;
            s += u; s2 += u * u; cnt += m;
        }
    }
#pragma unroll
    for (int off = 16; off > 0; off >>= 1) {
        s   += __shfl_xor_sync(0xffffffffu, s, off);
        s2  += __shfl_xor_sync(0xffffffffu, s2, off);
        cnt += __shfl_xor_sync(0xffffffffu, cnt, off);
    }
    __shared__ float rs[8], rs2[8], rc[8], bc[2];
    if (lane == 0) { rs[wid] = s; rs2[wid] = s2; rc[wid] = cnt; }
    __syncthreads();
    if (threadIdx.x == 0) {
        float S = 0.f, S2 = 0.f, C = 0.f;
#pragma unroll
        for (int i = 0; i < 8; i++) { S += rs[i]; S2 += rs2[i]; C += rc[i]; }
        if (C == 0.f) C = 1.f;
        float mean = S / C;
        float var  = (S2 - 2.f * mean * S + (float)N_ * mean * mean) / C;
        bc[0] = mean;
        bc[1] = rsqrtf(var + 1e-5f);
    }
    __syncthreads();
    float mean = bc[0], rstd = bc[1];
    float sc = scale[h], sh = shift[h];
    for (int n = threadIdx.x; n < N_; n += 256) {
        int g = b * N_ + n;
        float m = mask[g];
        float o = 0.f;
        if (m != 0.f) {
            float vc = g_vcnt[g];
            if (vc == 0.f) vc = 1.f;
            float u = (atom[g * H_ + h] + g_msum[g * H_ + h] / vc) * m;
            o = ((u - mean) * rstd * sc + sh) * m;
        }
        out[g * H_ + h] = o;
    }
}

// ------------------------------------------------- kernel 4: tuple tail copies
__global__ void tail_kernel(const float* __restrict__ mask, const float* __restrict__ dist,
                            const int* __restrict__ eidx, float* __restrict__ out,
                            int out_size) {
    int i = blockIdx.x * blockDim.x + threadIdx.x;
    const int off0 = NODES * H_;
    int j = i;
    if (j < NODES) {
        int o = off0 + j;
        if (o < out_size) out[o] = mask[j];
        return;
    }
    j -= NODES;
    if (j < EDGES) {
        int o = off0 + NODES + j;
        if (o < out_size) out[o] = dist[j];
        return;
    }
    j -= EDGES;
    if (j < EDGES) {
        int o = off0 + NODES + EDGES + j;
        if (o < out_size) out[o] = (float)eidx[j];
    }
}

// ------------------------------------------------- launch
extern "C" void kernel_launch(void* const* d_in, const int* in_sizes, int n_in,
                              void* d_out, int out_size) {
    const float* atom  = (const float*)d_in[0];
    const float* mask  = (const float*)d_in[1];
    const float* dist  = (const float*)d_in[2];
    const int*   eidx  = (const int*)d_in[3];
    const float* W0    = (const float*)d_in[4];
    const float* b0    = (const float*)d_in[5];
    const float* W1    = (const float*)d_in[6];
    const float* b1    = (const float*)d_in[7];
    const float* W2    = (const float*)d_in[8];
    const float* b2    = (const float*)d_in[9];
    const float* scale = (const float*)d_in[10];
    const float* shift = (const float*)d_in[11];
    float* out = (float*)d_out;

    cudaFuncSetAttribute(proj_kernel, cudaFuncAttributeMaxDynamicSharedMemorySize, SMEM_BYTES);
    cudaFuncSetAttribute(edge_kernel, cudaFuncAttributeMaxDynamicSharedMemorySize, SMEM_BYTES);

    proj_kernel<<<NODES / 128, 256, SMEM_BYTES>>>(atom, mask, W0, b0);
    edge_kernel<<<NTILES, 256, SMEM_BYTES>>>(dist, eidx, W0, W1, b1, W2, b2);
    norm_kernel<<<B_ * H_, 256>>>(atom, mask, scale, shift, out);
    int tail_n = NODES + 2 * EDGES;
    tail_kernel<<<(tail_n + 255) / 256, 256>>>(mask, dist, eidx, out, out_size);
}

// round 2
// speedup vs baseline: 1.3459x; 1.3459x over previous
#include <cuda_runtime.h>
#include <cstdint>

// Problem constants
#define B_      4
#define N_      4096
#define K_      32
#define H_      128
#define NODES   (B_ * N_)        // 16384
#define EDGES   (NODES * K_)     // 524288
#define LDS_    132              // padded row stride in floats
#define NTILES  (NODES / 4)      // 4096 tiles of 128 edges (4 nodes)
#define NCHUNK  32               // node chunks per batch for norm (4096/128)

static const int SMEM_BYTES = 3 * 128 * LDS_ * 4;  // 202752 B: sA + sW1 + sW2

// Scratch (no cudaMalloc allowed)
__device__ float g_P[NODES * H_];     // enc @ W0[:H]
__device__ float g_S[NODES * H_];     // enc @ W0[H:2H] + b0
__device__ float g_msum[NODES * H_];  // sum of valid messages per node
__device__ float g_vcnt[NODES];       // valid edge count per node
__device__ float g_ps [B_ * NCHUNK * H_];  // partial sums
__device__ float g_ps2[B_ * NCHUNK * H_];  // partial sum-of-squares
__device__ float g_pc [B_ * NCHUNK];       // partial mask counts

// ---------------------------------------------------------------- helpers
__device__ __forceinline__ float to_tf32(float x) {
    uint32_t u;
    asm("cvt.rna.tf32.f32 %0, %1;" : "=r"(u) : "f"(x));
    return __uint_as_float(u);
}
__device__ __forceinline__ float gelu_erf(float x) {
    return 0.5f * x * (1.0f + erff(x * 0.70710678118654752f));
}
__device__ __forceinline__ void mma8(float* c, const uint32_t* a, const uint32_t* b) {
    asm volatile(
        "mma.sync.aligned.m16n8k8.row.col.f32.tf32.tf32.f32 "
        "{%0,%1,%2,%3},{%4,%5,%6,%7},{%8,%9},{%0,%1,%2,%3};\n"
        : "+f"(c[0]), "+f"(c[1]), "+f"(c[2]), "+f"(c[3])
        : "r"(a[0]), "r"(a[1]), "r"(a[2]), "r"(a[3]), "r"(b[0]), "r"(b[1]));
}

// 8-warp variant (proj kernel): warp tile 32 rows x 64 cols, K=128.
__device__ __forceinline__ void warp_gemm64(const float* __restrict__ sAv,
                                            const float* __restrict__ sWv,
                                            float acc[2][8][4],
                                            int wm, int wn, int gid, int tig) {
#pragma unroll 4
    for (int k0 = 0; k0 < H_; k0 += 8) {
        uint32_t a[2][4];
#pragma unroll
        for (int i = 0; i < 2; i++) {
            const float* ap = sAv + (wm * 32 + i * 16 + gid) * LDS_ + k0;
            a[i][0] = __float_as_uint(ap[tig]);
            a[i][1] = __float_as_uint(ap[8 * LDS_ + tig]);
            a[i][2] = __float_as_uint(ap[tig + 4]);
            a[i][3] = __float_as_uint(ap[8 * LDS_ + tig + 4]);
        }
#pragma unroll
        for (int j = 0; j < 8; j++) {
            const float* bp = sWv + (wn * 64 + j * 8 + gid) * LDS_ + k0;
            uint32_t b[2] = {__float_as_uint(bp[tig]), __float_as_uint(bp[tig + 4])};
            mma8(acc[0][j], a[0], b);
            mma8(acc[1][j], a[1], b);
        }
    }
}

// 16-warp variant (edge kernel): warp tile 32 rows x 32 cols, K=128.
__device__ __forceinline__ void warp_gemm32(const float* __restrict__ sAv,
                                            const float* __restrict__ sWv,
                                            float acc[2][4][4],
                                            int wm, int wn, int gid, int tig) {
#pragma unroll 4
    for (int k0 = 0; k0 < H_; k0 += 8) {
        uint32_t a[2][4];
#pragma unroll
        for (int i = 0; i < 2; i++) {
            const float* ap = sAv + (wm * 32 + i * 16 + gid) * LDS_ + k0;
            a[i][0] = __float_as_uint(ap[tig]);
            a[i][1] = __float_as_uint(ap[8 * LDS_ + tig]);
            a[i][2] = __float_as_uint(ap[tig + 4]);
            a[i][3] = __float_as_uint(ap[8 * LDS_ + tig + 4]);
        }
#pragma unroll
        for (int j = 0; j < 4; j++) {
            const float* bp = sWv + (wn * 32 + j * 8 + gid) * LDS_ + k0;
            uint32_t b[2] = {__float_as_uint(bp[tig]), __float_as_uint(bp[tig + 4])};
            mma8(acc[0][j], a[0], b);
            mma8(acc[1][j], a[1], b);
        }
    }
}

// ------------------------------------------------- kernel 1: node projections
// P = (atom*mask) @ W0a ; S = (atom*mask) @ W0b + b0.  128 rows per CTA.
__global__ void __launch_bounds__(256, 1)
proj_kernel(const float* __restrict__ atom, const float* __restrict__ mask,
            const float* __restrict__ W0, const float* __restrict__ b0) {
    extern __shared__ float smem[];
    float* sA  = smem;
    float* sWa = smem + 128 * LDS_;
    float* sWb = smem + 2 * 128 * LDS_;
    __shared__ float sB0[128];

    int t = threadIdx.x, lane = t & 31, w = t >> 5;
    int wm = w >> 1, wn = w & 1, gid = lane >> 2, tig = lane & 3;

    if (t < 128) sB0[t] = b0[t];
    for (int i = t; i < 128 * 128; i += 256) {
        int k = i >> 7, n = i & 127;
        sWa[n * LDS_ + k] = to_tf32(W0[i]);                // rows 0..127
        sWb[n * LDS_ + k] = to_tf32(W0[128 * 128 + i]);    // rows 128..255
    }
    {   // load A tile (masked encodings), tf32-rounded
        int r = t >> 1;
        int grow = blockIdx.x * 128 + r;
        float m = mask[grow];
        int c0 = (t & 1) * 64;
        const float4* src = (const float4*)(atom + (size_t)grow * H_);
#pragma unroll 4
        for (int c = c0; c < c0 + 64; c += 4) {
            float4 a = src[c >> 2];
            float4 o;
            o.x = to_tf32(a.x * m); o.y = to_tf32(a.y * m);
            o.z = to_tf32(a.z * m); o.w = to_tf32(a.w * m);
            *(float4*)(sA + r * LDS_ + c) = o;
        }
    }
    __syncthreads();

    float acc[2][8][4];
#pragma unroll
    for (int i = 0; i < 2; i++)
#pragma unroll
        for (int j = 0; j < 8; j++)
#pragma unroll
            for (int q = 0; q < 4; q++) acc[i][j][q] = 0.f;
    warp_gemm64(sA, sWa, acc, wm, wn, gid, tig);
#pragma unroll
    for (int i = 0; i < 2; i++)
#pragma unroll
        for (int j = 0; j < 8; j++) {
            int col = wn * 64 + j * 8 + 2 * tig;
            int r = blockIdx.x * 128 + wm * 32 + i * 16 + gid;
            *(float2*)(g_P + (size_t)r * H_ + col)       = make_float2(acc[i][j][0], acc[i][j][1]);
            *(float2*)(g_P + (size_t)(r + 8) * H_ + col) = make_float2(acc[i][j][2], acc[i][j][3]);
        }
#pragma unroll
    for (int i = 0; i < 2; i++)
#pragma unroll
        for (int j = 0; j < 8; j++)
#pragma unroll
            for (int q = 0; q < 4; q++) acc[i][j][q] = 0.f;
    warp_gemm64(sA, sWb, acc, wm, wn, gid, tig);
#pragma unroll
    for (int i = 0; i < 2; i++)
#pragma unroll
        for (int j = 0; j < 8; j++) {
            int col = wn * 64 + j * 8 + 2 * tig;
            int r = blockIdx.x * 128 + wm * 32 + i * 16 + gid;
            float be = sB0[col], bo = sB0[col + 1];
            *(float2*)(g_S + (size_t)r * H_ + col)       = make_float2(acc[i][j][0] + be, acc[i][j][1] + bo);
            *(float2*)(g_S + (size_t)(r + 8) * H_ + col) = make_float2(acc[i][j][2] + be, acc[i][j][3] + bo);
        }
}

// ------------------------------------------------- kernel 2: persistent fused edge MLP
// Weights loaded ONCE per CTA; loop over tiles. 512 threads = 16 warps.
// Tile = 128 edges = 4 nodes.  h0 = gelu(P[src]+S[self]+d*w0c) -> h1 = gelu(h0@W1+b1)
// -> h2 = gelu(h1@W2+b2) * valid -> per-node column sums into g_msum.
__global__ void __launch_bounds__(512, 1)
edge_kernel(const float* __restrict__ dist, const int* __restrict__ eidx,
            const float* __restrict__ W0, const float* __restrict__ W1,
            const float* __restrict__ b1, const float* __restrict__ W2,
            const float* __restrict__ b2) {
    extern __shared__ float smem[];
    float* sA  = smem;
    float* sW1 = smem + 128 * LDS_;
    float* sW2 = smem + 2 * 128 * LDS_;
    __shared__ float sValid[128];
    __shared__ float sW0c[128];
    __shared__ float sB1[128];
    __shared__ float sB2[128];

    int t = threadIdx.x, lane = t & 31, w = t >> 5;
    int wm = w >> 2, wn = w & 3, gid = lane >> 2, tig = lane & 3;
    int sub = t & 7, ebase = t >> 3;   // 8 lanes cover one 128B row segment

    if (t < 128) {
        sW0c[t] = W0[256 * 128 + t];
        sB1[t]  = b1[t];
        sB2[t]  = b2[t];
    }
    // one-time weight staging (transposed [n][k], tf32-rounded)
    for (int i = t; i < 128 * 128; i += 512) {
        int k = i >> 7, n = i & 127;
        sW1[n * LDS_ + k] = to_tf32(W1[i]);
        sW2[n * LDS_ + k] = to_tf32(W2[i]);
    }
    __syncthreads();

    for (int tile = blockIdx.x; tile < NTILES; tile += gridDim.x) {
        // ---- phase A: gather + layer-1 epilogue -> h0 tile in sA
#pragma unroll
        for (int rr = 0; rr < 2; rr++) {
            int e = ebase + rr * 64;
            int gnode = tile * 4 + (e >> 5);
            int eid = gnode * K_ + (e & 31);
            int idx = __ldg(eidx + eid);
            float valid = (idx >= 0) ? 1.0f : 0.0f;
            int src = (gnode & ~(N_ - 1)) + (idx >= 0 ? idx : 0);
            float d = __ldg(dist + eid);
            if (sub == 0) sValid[e] = valid;
            const float4* pp = (const float4*)(g_P + (size_t)src * H_);
            const float4* sp = (const float4*)(g_S + (size_t)gnode * H_);
#pragma unroll
            for (int it = 0; it < 4; it++) {
                int c = it * 32 + sub * 4;
                float4 p = pp[c >> 2];
                float4 s = sp[c >> 2];
                float4 o;
                o.x = to_tf32(gelu_erf(p.x + s.x + d * sW0c[c]));
                o.y = to_tf32(gelu_erf(p.y + s.y + d * sW0c[c + 1]));
                o.z = to_tf32(gelu_erf(p.z + s.z + d * sW0c[c + 2]));
                o.w = to_tf32(gelu_erf(p.w + s.w + d * sW0c[c + 3]));
                *(float4*)(sA + e * LDS_ + c) = o;
            }
        }
        __syncthreads();

        if (t < 4) {   // valid counts, one node each
            float c = 0.f;
#pragma unroll
            for (int kk = 0; kk < 32; kk++) c += sValid[t * 32 + kk];
            g_vcnt[tile * 4 + t] = c;
        }

        // ---- layer 2
        float acc[2][4][4];
#pragma unroll
        for (int i = 0; i < 2; i++)
#pragma unroll
            for (int j = 0; j < 4; j++)
#pragma unroll
                for (int q = 0; q < 4; q++) acc[i][j][q] = 0.f;
        warp_gemm32(sA, sW1, acc, wm, wn, gid, tig);
        __syncthreads();   // all reads of h0 done
#pragma unroll
        for (int i = 0; i < 2; i++)
#pragma unroll
            for (int j = 0; j < 4; j++) {
                int col = wn * 32 + j * 8 + 2 * tig;
                int r0 = wm * 32 + i * 16 + gid;
                sA[r0 * LDS_ + col]           = to_tf32(gelu_erf(acc[i][j][0] + sB1[col]));
                sA[r0 * LDS_ + col + 1]       = to_tf32(gelu_erf(acc[i][j][1] + sB1[col + 1]));
                sA[(r0 + 8) * LDS_ + col]     = to_tf32(gelu_erf(acc[i][j][2] + sB1[col]));
                sA[(r0 + 8) * LDS_ + col + 1] = to_tf32(gelu_erf(acc[i][j][3] + sB1[col + 1]));
            }
        __syncthreads();   // h1 visible

        // ---- layer 3
#pragma unroll
        for (int i = 0; i < 2; i++)
#pragma unroll
            for (int j = 0; j < 4; j++)
#pragma unroll
                for (int q = 0; q < 4; q++) acc[i][j][q] = 0.f;
        warp_gemm32(sA, sW2, acc, wm, wn, gid, tig);

        // ---- epilogue: gelu + valid mask + sum over 32 edges of node wm
        int gout = tile * 4 + wm;
#pragma unroll
        for (int j = 0; j < 4; j++) {
            int col = wn * 32 + j * 8 + 2 * tig;
            float be = sB2[col], bo = sB2[col + 1];
            float se = 0.f, so = 0.f;
#pragma unroll
            for (int i = 0; i < 2; i++) {
                int r0 = wm * 32 + i * 16 + gid;
                float v0 = sValid[r0], v1 = sValid[r0 + 8];
                se += gelu_erf(acc[i][j][0] + be) * v0 + gelu_erf(acc[i][j][2] + be) * v1;
                so += gelu_erf(acc[i][j][1] + bo) * v0 + gelu_erf(acc[i][j][3] + bo) * v1;
            }
            se += __shfl_xor_sync(0xffffffffu, se, 16);
            so += __shfl_xor_sync(0xffffffffu, so, 16);
            se += __shfl_xor_sync(0xffffffffu, se, 8);
            so += __shfl_xor_sync(0xffffffffu, so, 8);
            se += __shfl_xor_sync(0xffffffffu, se, 4);
            so += __shfl_xor_sync(0xffffffffu, so, 4);
            if (gid == 0) *(float2*)(g_msum + (size_t)gout * H_ + col) = make_float2(se, so);
        }
        __syncthreads();   // done with sA/sValid before next tile's phase A
    }
}

// ------------------------------------------------- kernel 3a: per-chunk partial stats (coalesced)
__global__ void __launch_bounds__(256)
norm1_kernel(const float* __restrict__ atom, const float* __restrict__ mask) {
    int b = blockIdx.x >> 5, chunk = blockIdx.x & 31;
    int t = threadIdx.x, h = t & 127, half = t >> 7;
    int n0 = chunk * 128;

    float s = 0.f, s2 = 0.f;
    for (int n = n0 + half; n < n0 + 128; n += 2) {
        int g = b * N_ + n;
        float m = mask[g];
        float vc = fmaxf(g_vcnt[g], 1.0f);
        float u = (atom[(size_t)g * H_ + h] + g_msum[(size_t)g * H_ + h] / vc) * m;
        s += u; s2 += u * u;
    }
    __shared__ float sS[256], sS2[256];
    sS[t] = s; sS2[t] = s2;
    __syncthreads();
    if (t < 128) {
        g_ps [(b * NCHUNK + chunk) * H_ + t] = sS[t] + sS[t + 128];
        g_ps2[(b * NCHUNK + chunk) * H_ + t] = sS2[t] + sS2[t + 128];
    }
    if (t < 32) {
        float c = 0.f;
#pragma unroll
        for (int n = n0 + t; n < n0 + 128; n += 32) c += mask[b * N_ + n];
#pragma unroll
        for (int off = 16; off > 0; off >>= 1) c += __shfl_xor_sync(0xffffffffu, c, off);
        if (t == 0) g_pc[b * NCHUNK + chunk] = c;
    }
}

// ------------------------------------------------- kernel 3b: finalize + normalize (coalesced)
__global__ void __launch_bounds__(256)
norm2_kernel(const float* __restrict__ atom, const float* __restrict__ mask,
             const float* __restrict__ scale, const float* __restrict__ shift,
             float* __restrict__ out) {
    int b = blockIdx.x >> 5, chunk = blockIdx.x & 31;
    int t = threadIdx.x, h = t & 127, half = t >> 7;
    __shared__ float sMean[128], sRstd[128];

    if (t < 128) {
        float S = 0.f, S2 = 0.f, C = 0.f;
#pragma unroll 8
        for (int c = 0; c < NCHUNK; c++) {
            S  += g_ps [(b * NCHUNK + c) * H_ + t];
            S2 += g_ps2[(b * NCHUNK + c) * H_ + t];
            C  += g_pc[b * NCHUNK + c];
        }
        if (C == 0.f) C = 1.f;
        float mean = S / C;
        float var  = (S2 - 2.f * mean * S + (float)N_ * mean * mean) / C;
        sMean[t] = mean;
        sRstd[t] = rsqrtf(var + 1e-5f);
    }
    __syncthreads();
    float mean = sMean[h], rstd = sRstd[h];
    float sc = scale[h], sh = shift[h];
    int n0 = chunk * 128;
    for (int n = n0 + half; n < n0 + 128; n += 2) {
        int g = b * N_ + n;
        float m = mask[g];
        float vc = fmaxf(g_vcnt[g], 1.0f);
        float u = (atom[(size_t)g * H_ + h] + g_msum[(size_t)g * H_ + h] / vc) * m;
        out[(size_t)g * H_ + h] = ((u - mean) * rstd * sc + sh) * m;
    }
}

// ------------------------------------------------- kernel 4: tuple tail copies
__global__ void tail_kernel(const float* __restrict__ mask, const float* __restrict__ dist,
                            const int* __restrict__ eidx, float* __restrict__ out,
                            int out_size) {
    int i = blockIdx.x * blockDim.x + threadIdx.x;
    const int off0 = NODES * H_;
    int j = i;
    if (j < NODES) {
        int o = off0 + j;
        if (o < out_size) out[o] = mask[j];
        return;
    }
    j -= NODES;
    if (j < EDGES) {
        int o = off0 + NODES + j;
        if (o < out_size) out[o] = dist[j];
        return;
    }
    j -= EDGES;
    if (j < EDGES) {
        int o = off0 + NODES + EDGES + j;
        if (o < out_size) out[o] = (float)eidx[j];
    }
}

// ------------------------------------------------- launch
extern "C" void kernel_launch(void* const* d_in, const int* in_sizes, int n_in,
                              void* d_out, int out_size) {
    const float* atom  = (const float*)d_in[0];
    const float* mask  = (const float*)d_in[1];
    const float* dist  = (const float*)d_in[2];
    const int*   eidx  = (const int*)d_in[3];
    const float* W0    = (const float*)d_in[4];
    const float* b0    = (const float*)d_in[5];
    const float* W1    = (const float*)d_in[6];
    const float* b1    = (const float*)d_in[7];
    const float* W2    = (const float*)d_in[8];
    const float* b2    = (const float*)d_in[9];
    const float* scale = (const float*)d_in[10];
    const float* shift = (const float*)d_in[11];
    float* out = (float*)d_out;

    cudaFuncSetAttribute(proj_kernel, cudaFuncAttributeMaxDynamicSharedMemorySize, SMEM_BYTES);
    cudaFuncSetAttribute(edge_kernel, cudaFuncAttributeMaxDynamicSharedMemorySize, SMEM_BYTES);

    proj_kernel<<<NODES / 128, 256, SMEM_BYTES>>>(atom, mask, W0, b0);
    edge_kernel<<<148, 512, SMEM_BYTES>>>(dist, eidx, W0, W1, b1, W2, b2);
    norm1_kernel<<<B_ * NCHUNK, 256>>>(atom, mask);
    norm2_kernel<<<B_ * NCHUNK, 256>>>(atom, mask, scale, shift, out);
    int tail_n = NODES + 2 * EDGES;
    tail_kernel<<<(tail_n + 255) / 256, 256>>>(mask, dist, eidx, out, out_size);
}